// round 1
// baseline (speedup 1.0000x reference)
#include <cuda_runtime.h>
#include <math.h>

#define BB 4
#define NN 8192
#define CC 256
#define HH 8
#define DD 64
#define HD 512
#define NCHUNK 16
#define CHK (NN / NCHUNK)   // 512

// Scratch (allocation-free rule: __device__ globals)
__device__ float g_q[BB * HH * NN * DD];            // 67 MB, layout [bh][n][d]
__device__ float g_k[BB * HH * NN * DD];
__device__ float g_v[BB * HH * NN * DD];
__device__ float g_u[BB * HH * NN * DD];
__device__ float g_part[NCHUNK * BB * HH * DD * DD]; // partial dots
__device__ float g_dots[BB * HH * DD * DD];

// ---------------------------------------------------------------------------
// Kernel A: QKV projection.  C[m, j] = X[m,:] . W[j,:]   (W row-major [512,256])
// 128x128 block tile, 8x8 per-thread microtile, BK=16.
// Output scattered into [bh][n][d] layout.
// ---------------------------------------------------------------------------
__global__ __launch_bounds__(256) void qkv_gemm(
    const float* __restrict__ X,
    const float* __restrict__ Wq,
    const float* __restrict__ Wk,
    const float* __restrict__ Wv)
{
    __shared__ float Xs[16][129];
    __shared__ float Ws[16][129];

    const int m0 = blockIdx.y * 128;
    const int jb = blockIdx.x;          // 0..11 (12 col-blocks of 128 over 1536)
    const int which = jb >> 2;          // 0:q 1:k 2:v (512/128 = 4 blocks each)
    const float* W = (which == 0) ? Wq : (which == 1) ? Wk : Wv;
    float* dst = (which == 0) ? g_q : (which == 1) ? g_k : g_v;
    const int j0 = (jb & 3) * 128;      // column offset within the 512 of this matrix

    const int tid = threadIdx.x;
    const int tx = tid & 15;
    const int ty = tid >> 4;
    const int lk = tid & 15;            // k within BK tile
    const int lm = tid >> 4;            // row base

    float acc[8][8];
    #pragma unroll
    for (int i = 0; i < 8; i++)
        #pragma unroll
        for (int j = 0; j < 8; j++) acc[i][j] = 0.0f;

    for (int kk = 0; kk < CC; kk += 16) {
        #pragma unroll
        for (int p = 0; p < 8; p++) {
            int m = lm + p * 16;
            Xs[lk][m] = X[(size_t)(m0 + m) * CC + kk + lk];
            Ws[lk][m] = W[(size_t)(j0 + m) * CC + kk + lk];
        }
        __syncthreads();
        #pragma unroll
        for (int k = 0; k < 16; k++) {
            float a[8], w[8];
            #pragma unroll
            for (int i = 0; i < 8; i++) a[i] = Xs[k][ty + 16 * i];
            #pragma unroll
            for (int j = 0; j < 8; j++) w[j] = Ws[k][tx + 16 * j];
            #pragma unroll
            for (int i = 0; i < 8; i++)
                #pragma unroll
                for (int j = 0; j < 8; j++) acc[i][j] += a[i] * w[j];
        }
        __syncthreads();
    }

    #pragma unroll
    for (int i = 0; i < 8; i++) {
        int m = m0 + ty + 16 * i;           // m = b*NN + n
        int b = m >> 13;                    // NN = 8192 = 2^13
        int n = m & (NN - 1);
        #pragma unroll
        for (int j = 0; j < 8; j++) {
            int col = j0 + tx + 16 * j;     // 0..511
            int h = col >> 6;
            int d = col & 63;
            dst[(((size_t)(b * HH + h)) * NN + n) * DD + d] = acc[i][j];
        }
    }
}

// ---------------------------------------------------------------------------
// Kernel B: instance-norm(K,V over D=64) + 2D RoPE(Q,K).  One warp per (b,h,n).
// Thread lane holds d=lane and d=lane+32 (x-half uses fx, y-half uses fy).
// Rotation partner is lane ^ 16.
// ---------------------------------------------------------------------------
__global__ __launch_bounds__(256) void norm_rope(const float* __restrict__ pos)
{
    const int warp = threadIdx.x >> 5;
    const int lane = threadIdx.x & 31;
    const size_t bhn = (size_t)blockIdx.x * 8 + warp;   // < BB*HH*NN
    const int n = (int)(bhn & (NN - 1));

    const float px = pos[n * 2 + 0];
    const float py = pos[n * 2 + 1];
    const int j = lane & 15;
    // inv_freq[j] = 10000^(-j/16); angle = (pos/MIN_FREQ) * inv_freq, MIN_FREQ=1/64
    const float invf = exp2f(-(float)j * (13.2877123795494f / 16.0f));
    const float thx = px * 64.0f * invf;
    const float thy = py * 64.0f * invf;
    float cx, sx, cy, sy;
    sincosf(thx, &sx, &cx);
    sincosf(thy, &sy, &cy);
    const float sgn = (lane < 16) ? -1.0f : 1.0f;
    const unsigned FULL = 0xffffffffu;

    const size_t base = bhn * DD;

    // Q: rope only
    {
        float q0 = g_q[base + lane];
        float q1 = g_q[base + 32 + lane];
        float q0p = __shfl_xor_sync(FULL, q0, 16);
        float q1p = __shfl_xor_sync(FULL, q1, 16);
        g_q[base + lane]      = q0 * cx + sgn * q0p * sx;
        g_q[base + 32 + lane] = q1 * cy + sgn * q1p * sy;
    }
    // K: norm then rope
    {
        float k0 = g_k[base + lane];
        float k1 = g_k[base + 32 + lane];
        float s = k0 + k1, ss = k0 * k0 + k1 * k1;
        #pragma unroll
        for (int o = 16; o > 0; o >>= 1) {
            s  += __shfl_xor_sync(FULL, s, o);
            ss += __shfl_xor_sync(FULL, ss, o);
        }
        float mean = s * (1.0f / 64.0f);
        float var  = ss * (1.0f / 64.0f) - mean * mean;
        float inv  = rsqrtf(var + 1e-5f);
        k0 = (k0 - mean) * inv;
        k1 = (k1 - mean) * inv;
        float k0p = __shfl_xor_sync(FULL, k0, 16);
        float k1p = __shfl_xor_sync(FULL, k1, 16);
        g_k[base + lane]      = k0 * cx + sgn * k0p * sx;
        g_k[base + 32 + lane] = k1 * cy + sgn * k1p * sy;
    }
    // V: norm only
    {
        float v0 = g_v[base + lane];
        float v1 = g_v[base + 32 + lane];
        float s = v0 + v1, ss = v0 * v0 + v1 * v1;
        #pragma unroll
        for (int o = 16; o > 0; o >>= 1) {
            s  += __shfl_xor_sync(FULL, s, o);
            ss += __shfl_xor_sync(FULL, ss, o);
        }
        float mean = s * (1.0f / 64.0f);
        float var  = ss * (1.0f / 64.0f) - mean * mean;
        float inv  = rsqrtf(var + 1e-5f);
        g_v[base + lane]      = (v0 - mean) * inv;
        g_v[base + 32 + lane] = (v1 - mean) * inv;
    }
}

// ---------------------------------------------------------------------------
// Kernel C: partial dots[bh][d][e] = sum over 512-token chunk of k[n][d]*v[n][e]
// One block per (chunk, bh). Deterministic two-stage reduction (no atomics).
// ---------------------------------------------------------------------------
__global__ __launch_bounds__(256) void kv_dots()
{
    __shared__ float Ks[16][64];
    __shared__ float Vs[16][64];

    const int chunk = blockIdx.x;   // 0..15
    const int bh = blockIdx.y;      // 0..31
    const int tid = threadIdx.x;
    const int tx = tid & 15;
    const int ty = tid >> 4;
    const int lt = tid >> 4;        // 0..15 token in stage
    const int ld4 = (tid & 15) * 4; // 4-float column group

    const size_t nb0 = ((size_t)bh * NN + (size_t)chunk * CHK) * DD;

    float acc[4][4];
    #pragma unroll
    for (int i = 0; i < 4; i++)
        #pragma unroll
        for (int j = 0; j < 4; j++) acc[i][j] = 0.0f;

    for (int s = 0; s < CHK; s += 16) {
        *(float4*)&Ks[lt][ld4] = *(const float4*)&g_k[nb0 + (size_t)(s + lt) * DD + ld4];
        *(float4*)&Vs[lt][ld4] = *(const float4*)&g_v[nb0 + (size_t)(s + lt) * DD + ld4];
        __syncthreads();
        #pragma unroll
        for (int t = 0; t < 16; t++) {
            float a[4], w[4];
            #pragma unroll
            for (int i = 0; i < 4; i++) a[i] = Ks[t][ty + 16 * i];
            #pragma unroll
            for (int j = 0; j < 4; j++) w[j] = Vs[t][tx + 16 * j];
            #pragma unroll
            for (int i = 0; i < 4; i++)
                #pragma unroll
                for (int j = 0; j < 4; j++) acc[i][j] += a[i] * w[j];
        }
        __syncthreads();
    }

    float* P = &g_part[((size_t)chunk * (BB * HH) + bh) * (DD * DD)];
    #pragma unroll
    for (int i = 0; i < 4; i++)
        #pragma unroll
        for (int j = 0; j < 4; j++)
            P[(ty + 16 * i) * DD + tx + 16 * j] = acc[i][j];
}

// Sum the 16 chunk partials (fixed order -> deterministic), fold in 1/N.
__global__ __launch_bounds__(256) void reduce_dots()
{
    const int i = blockIdx.x * 256 + threadIdx.x;   // < 32*4096 = 131072
    float s = 0.0f;
    #pragma unroll
    for (int c = 0; c < NCHUNK; c++)
        s += g_part[(size_t)c * (BB * HH * DD * DD) + i];
    g_dots[i] = s * (1.0f / (float)NN);
}

// ---------------------------------------------------------------------------
// Kernel D: u[bh][n][e] = sum_d q[bh][n][d] * dots[bh][d][e]   (dots pre-scaled)
// One block per (64-token tile, bh); dots resident in smem.
// ---------------------------------------------------------------------------
__global__ __launch_bounds__(256) void q_dots()
{
    __shared__ float Qs[64][68];   // padded for float4 align + bank spread
    __shared__ float Ds[64][64];

    const int bh = blockIdx.y;
    const int n0 = blockIdx.x * 64;
    const int tid = threadIdx.x;
    const int tx = tid & 15;
    const int ty = tid >> 4;
    const int lt = tid >> 4;
    const int ld4 = (tid & 15) * 4;

    #pragma unroll
    for (int r = 0; r < 4; r++)
        *(float4*)&Ds[lt + r * 16][ld4] =
            *(const float4*)&g_dots[(size_t)bh * (DD * DD) + (size_t)(lt + r * 16) * DD + ld4];
    #pragma unroll
    for (int r = 0; r < 4; r++)
        *(float4*)&Qs[lt + r * 16][ld4] =
            *(const float4*)&g_q[((size_t)bh * NN + n0 + lt + r * 16) * DD + ld4];
    __syncthreads();

    float acc[4][4];
    #pragma unroll
    for (int i = 0; i < 4; i++)
        #pragma unroll
        for (int j = 0; j < 4; j++) acc[i][j] = 0.0f;

    #pragma unroll
    for (int k = 0; k < 64; k++) {
        float a[4], w[4];
        #pragma unroll
        for (int i = 0; i < 4; i++) a[i] = Qs[ty + 16 * i][k];
        #pragma unroll
        for (int j = 0; j < 4; j++) w[j] = Ds[k][tx + 16 * j];
        #pragma unroll
        for (int i = 0; i < 4; i++)
            #pragma unroll
            for (int j = 0; j < 4; j++) acc[i][j] += a[i] * w[j];
    }

    #pragma unroll
    for (int i = 0; i < 4; i++)
        #pragma unroll
        for (int j = 0; j < 4; j++)
            g_u[((size_t)bh * NN + n0 + ty + 16 * i) * DD + tx + 16 * j] = acc[i][j];
}

// ---------------------------------------------------------------------------
// Kernel E: out[m, c] = sum_k u_gathered[m, k] * Wo[c, k] + bo[c]
// m = b*NN+n rows; k = h*64+d gathered from [bh][n][d] layout.
// 128x128 block tile, 8x8 microtile, BK=16.
// ---------------------------------------------------------------------------
__global__ __launch_bounds__(256) void out_gemm(
    const float* __restrict__ Wo,
    const float* __restrict__ bo,
    float* __restrict__ out)
{
    __shared__ float Us[16][129];
    __shared__ float Ws[16][129];

    const int m0 = blockIdx.y * 128;
    const int j0 = blockIdx.x * 128;
    const int tid = threadIdx.x;
    const int tx = tid & 15;
    const int ty = tid >> 4;
    const int lk = tid & 15;
    const int lm = tid >> 4;

    float acc[8][8];
    #pragma unroll
    for (int i = 0; i < 8; i++)
        #pragma unroll
        for (int j = 0; j < 8; j++) acc[i][j] = 0.0f;

    for (int kk = 0; kk < HD; kk += 16) {
        const int h = kk >> 6;
        const int d0 = kk & 63;
        #pragma unroll
        for (int p = 0; p < 8; p++) {
            int m = lm + p * 16;
            int mg = m0 + m;
            int b = mg >> 13;
            int n = mg & (NN - 1);
            Us[lk][m] = g_u[(((size_t)(b * HH + h)) * NN + n) * DD + d0 + lk];
            Ws[lk][m] = Wo[(size_t)(j0 + m) * HD + kk + lk];
        }
        __syncthreads();
        #pragma unroll
        for (int k = 0; k < 16; k++) {
            float a[8], w[8];
            #pragma unroll
            for (int i = 0; i < 8; i++) a[i] = Us[k][ty + 16 * i];
            #pragma unroll
            for (int j = 0; j < 8; j++) w[j] = Ws[k][tx + 16 * j];
            #pragma unroll
            for (int i = 0; i < 8; i++)
                #pragma unroll
                for (int j = 0; j < 8; j++) acc[i][j] += a[i] * w[j];
        }
        __syncthreads();
    }

    #pragma unroll
    for (int i = 0; i < 8; i++) {
        int mg = m0 + ty + 16 * i;          // = b*NN + n
        #pragma unroll
        for (int j = 0; j < 8; j++) {
            int col = j0 + tx + 16 * j;
            out[(size_t)mg * CC + col] = acc[i][j] + bo[col];
        }
    }
}

// ---------------------------------------------------------------------------
extern "C" void kernel_launch(void* const* d_in, const int* in_sizes, int n_in,
                              void* d_out, int out_size)
{
    const float* ux  = (const float*)d_in[0];   // (B,N,C)
    const float* pos = (const float*)d_in[1];   // (1,N,2)
    const float* Wq  = (const float*)d_in[2];   // (512,256)
    const float* Wk  = (const float*)d_in[3];
    const float* Wv  = (const float*)d_in[4];
    const float* Wo  = (const float*)d_in[5];   // (256,512)
    const float* bo  = (const float*)d_in[6];   // (256,)
    float* out = (float*)d_out;                 // (B,N,256)

    qkv_gemm<<<dim3(12, 256), 256>>>(ux, Wq, Wk, Wv);
    norm_rope<<<(BB * HH * NN) / 8, 256>>>(pos);
    kv_dots<<<dim3(NCHUNK, BB * HH), 256>>>();
    reduce_dots<<<(BB * HH * DD * DD) / 256, 256>>>();
    q_dots<<<dim3(NN / 64, BB * HH), 256>>>();
    out_gemm<<<dim3(CC / 128, (BB * NN) / 128), 256>>>(Wo, bo, out);
}

// round 2
// speedup vs baseline: 1.1715x; 1.1715x over previous
#include <cuda_runtime.h>
#include <math.h>

#define BB 4
#define NN 8192
#define CC 256
#define HH 8
#define DD 64
#define HD 512
#define NCHUNK 16
#define CHK (NN / NCHUNK)   // 512

typedef unsigned long long u64t;

// Scratch (allocation-free rule: __device__ globals)
__device__ float g_q[BB * HH * NN * DD];            // [bh][n][d]
__device__ float g_k[BB * HH * NN * DD];
__device__ float g_v[BB * HH * NN * DD];
__device__ float g_u[BB * HH * NN * DD];
__device__ float g_part[NCHUNK * BB * HH * DD * DD];
__device__ float g_dots[BB * HH * DD * DD];
__device__ float g_trig[NN * 64];                   // per n: cx[16] sx[16] cy[16] sy[16]

// ---- packed f32x2 helpers (Blackwell full-rate fp32 path) --------------------
__device__ __forceinline__ u64t ffma2(u64t a, u64t b, u64t c) {
    u64t d;
    asm("fma.rn.f32x2 %0, %1, %2, %3;" : "=l"(d) : "l"(a), "l"(b), "l"(c));
    return d;
}
__device__ __forceinline__ u64t pack2(float x) {
    u64t d;
    asm("mov.b64 %0, {%1, %1};" : "=l"(d) : "r"(__float_as_uint(x)));
    return d;
}
__device__ __forceinline__ void unpack2(u64t v, float& lo, float& hi) {
    unsigned a, b;
    asm("mov.b64 {%0, %1}, %2;" : "=r"(a), "=r"(b) : "l"(v));
    lo = __uint_as_float(a);
    hi = __uint_as_float(b);
}

// ---------------------------------------------------------------------------
// Trig table: per token n, 16 freqs: cx sx cy sy (precise sincosf, done once)
// ---------------------------------------------------------------------------
__global__ __launch_bounds__(256) void trig_init(const float* __restrict__ pos)
{
    const int idx = blockIdx.x * 256 + threadIdx.x;   // n*16 + j
    const int n = idx >> 4;
    const int j = idx & 15;
    const float invf = exp2f(-(float)j * (13.2877123795494f / 16.0f));
    const float px = pos[n * 2 + 0];
    const float py = pos[n * 2 + 1];
    float cx, sx, cy, sy;
    sincosf(px * 64.0f * invf, &sx, &cx);
    sincosf(py * 64.0f * invf, &sy, &cy);
    float* T = &g_trig[(size_t)n * 64];
    T[j] = cx; T[16 + j] = sx; T[32 + j] = cy; T[48 + j] = sy;
}

// ---------------------------------------------------------------------------
// Kernel A: QKV projection, f32x2 inner loop.
// 128x128 tile; thread: rows 2*ty+32*ip (+0/+1 packed), cols tx+16*j.
// ---------------------------------------------------------------------------
__global__ __launch_bounds__(256) void qkv_gemm(
    const float* __restrict__ X,
    const float* __restrict__ Wq,
    const float* __restrict__ Wk,
    const float* __restrict__ Wv)
{
    __shared__ __align__(16) float Xs[16][130];
    __shared__ __align__(16) float Ws[16][130];

    const int m0 = blockIdx.y * 128;
    const int jb = blockIdx.x;
    const int which = jb >> 2;
    const float* W = (which == 0) ? Wq : (which == 1) ? Wk : Wv;
    float* dst = (which == 0) ? g_q : (which == 1) ? g_k : g_v;
    const int j0 = (jb & 3) * 128;

    const int tid = threadIdx.x;
    const int tx = tid & 15;
    const int ty = tid >> 4;
    const int tk = tid & 3;     // float4 group in k
    const int tm = tid >> 2;    // 0..63

    u64t acc[4][8];
    #pragma unroll
    for (int ip = 0; ip < 4; ip++)
        #pragma unroll
        for (int j = 0; j < 8; j++) acc[ip][j] = 0ull;

    for (int kk = 0; kk < CC; kk += 16) {
        #pragma unroll
        for (int half = 0; half < 2; half++) {
            int m = tm + 64 * half;
            float4 xv = *(const float4*)&X[(size_t)(m0 + m) * CC + kk + 4 * tk];
            float4 wv = *(const float4*)&W[(size_t)(j0 + m) * CC + kk + 4 * tk];
            Xs[4 * tk + 0][m] = xv.x; Xs[4 * tk + 1][m] = xv.y;
            Xs[4 * tk + 2][m] = xv.z; Xs[4 * tk + 3][m] = xv.w;
            Ws[4 * tk + 0][m] = wv.x; Ws[4 * tk + 1][m] = wv.y;
            Ws[4 * tk + 2][m] = wv.z; Ws[4 * tk + 3][m] = wv.w;
        }
        __syncthreads();
        #pragma unroll
        for (int k = 0; k < 16; k++) {
            u64t a2[4], w2[8];
            #pragma unroll
            for (int ip = 0; ip < 4; ip++)
                a2[ip] = *(const u64t*)&Xs[k][2 * ty + 32 * ip];
            #pragma unroll
            for (int j = 0; j < 8; j++)
                w2[j] = pack2(Ws[k][tx + 16 * j]);
            #pragma unroll
            for (int ip = 0; ip < 4; ip++)
                #pragma unroll
                for (int j = 0; j < 8; j++)
                    acc[ip][j] = ffma2(a2[ip], w2[j], acc[ip][j]);
        }
        __syncthreads();
    }

    #pragma unroll
    for (int ip = 0; ip < 4; ip++) {
        #pragma unroll
        for (int j = 0; j < 8; j++) {
            float lo, hi;
            unpack2(acc[ip][j], lo, hi);
            const int col = j0 + tx + 16 * j;
            const int h = col >> 6;
            const int d = col & 63;
            #pragma unroll
            for (int hrow = 0; hrow < 2; hrow++) {
                int m = m0 + 2 * ty + 32 * ip + hrow;
                int b = m >> 13;
                int n = m & (NN - 1);
                dst[(((size_t)(b * HH + h)) * NN + n) * DD + d] = hrow ? hi : lo;
            }
        }
    }
}

// ---------------------------------------------------------------------------
// Kernel B: partial dots with FUSED instance-norm(K,V) + RoPE(K).
// Per block: (chunk, bh). Tokens staged 16 at a time, normalized in smem.
// ---------------------------------------------------------------------------
__global__ __launch_bounds__(256) void kv_dots()
{
    __shared__ __align__(16) float Ks[16][64];
    __shared__ __align__(16) float Vs[16][64];

    const int chunk = blockIdx.x;
    const int bh = blockIdx.y;
    const int tid = threadIdx.x;
    const int w = tid >> 5;
    const int lane = tid & 31;
    const int jf = lane & 15;
    const float sgn = (lane < 16) ? -1.0f : 1.0f;
    const unsigned FULL = 0xffffffffu;

    const int tx = tid & 15;
    const int ty = tid >> 4;
    const int lt = tid >> 4;
    const int ld4 = (tid & 15) * 4;

    const size_t nbase = (size_t)bh * NN + (size_t)chunk * CHK;

    u64t acc[4][2];
    #pragma unroll
    for (int i = 0; i < 4; i++) { acc[i][0] = 0ull; acc[i][1] = 0ull; }

    for (int s = 0; s < CHK; s += 16) {
        *(float4*)&Ks[lt][ld4] = *(const float4*)&g_k[(nbase + s + lt) * DD + ld4];
        *(float4*)&Vs[lt][ld4] = *(const float4*)&g_v[(nbase + s + lt) * DD + ld4];
        __syncthreads();

        #pragma unroll
        for (int r = 0; r < 2; r++) {
            const int row = w * 2 + r;
            const int n = chunk * CHK + s + row;
            const float* T = &g_trig[(size_t)n * 64];
            const float cx = T[jf], sx = T[16 + jf], cy = T[32 + jf], sy = T[48 + jf];
            // K: norm + rope
            {
                float k0 = Ks[row][lane], k1 = Ks[row][32 + lane];
                float su = k0 + k1, ss = k0 * k0 + k1 * k1;
                #pragma unroll
                for (int o = 16; o > 0; o >>= 1) {
                    su += __shfl_xor_sync(FULL, su, o);
                    ss += __shfl_xor_sync(FULL, ss, o);
                }
                float mean = su * (1.0f / 64.0f);
                float var = ss * (1.0f / 64.0f) - mean * mean;
                float inv = rsqrtf(var + 1e-5f);
                k0 = (k0 - mean) * inv;
                k1 = (k1 - mean) * inv;
                float k0p = __shfl_xor_sync(FULL, k0, 16);
                float k1p = __shfl_xor_sync(FULL, k1, 16);
                Ks[row][lane]      = k0 * cx + sgn * k0p * sx;
                Ks[row][32 + lane] = k1 * cy + sgn * k1p * sy;
            }
            // V: norm only
            {
                float v0 = Vs[row][lane], v1 = Vs[row][32 + lane];
                float su = v0 + v1, ss = v0 * v0 + v1 * v1;
                #pragma unroll
                for (int o = 16; o > 0; o >>= 1) {
                    su += __shfl_xor_sync(FULL, su, o);
                    ss += __shfl_xor_sync(FULL, ss, o);
                }
                float mean = su * (1.0f / 64.0f);
                float var = ss * (1.0f / 64.0f) - mean * mean;
                float inv = rsqrtf(var + 1e-5f);
                Vs[row][lane]      = (v0 - mean) * inv;
                Vs[row][32 + lane] = (v1 - mean) * inv;
            }
        }
        __syncthreads();

        #pragma unroll
        for (int t = 0; t < 16; t++) {
            float4 av = *(const float4*)&Ks[t][ty * 4];
            float4 wv = *(const float4*)&Vs[t][tx * 4];
            u64t w2[2];
            w2[0] = ((const u64t*)&wv)[0];
            w2[1] = ((const u64t*)&wv)[1];
            float a[4] = {av.x, av.y, av.z, av.w};
            #pragma unroll
            for (int i = 0; i < 4; i++) {
                u64t ap = pack2(a[i]);
                acc[i][0] = ffma2(ap, w2[0], acc[i][0]);
                acc[i][1] = ffma2(ap, w2[1], acc[i][1]);
            }
        }
        __syncthreads();
    }

    float* P = &g_part[((size_t)chunk * (BB * HH) + bh) * (DD * DD)];
    #pragma unroll
    for (int i = 0; i < 4; i++) {
        float4 ov;
        unpack2(acc[i][0], ov.x, ov.y);
        unpack2(acc[i][1], ov.z, ov.w);
        *(float4*)&P[(ty * 4 + i) * DD + tx * 4] = ov;
    }
}

// Sum the 16 chunk partials (fixed order -> deterministic), fold in 1/N.
__global__ __launch_bounds__(256) void reduce_dots()
{
    const int i = blockIdx.x * 256 + threadIdx.x;
    float s = 0.0f;
    #pragma unroll
    for (int c = 0; c < NCHUNK; c++)
        s += g_part[(size_t)c * (BB * HH * DD * DD) + i];
    g_dots[i] = s * (1.0f / (float)NN);
}

// ---------------------------------------------------------------------------
// Kernel C: u = rope(q_raw) @ dots, rope fused (trig table), f32x2 MMA.
// ---------------------------------------------------------------------------
__global__ __launch_bounds__(256) void q_dots()
{
    __shared__ __align__(16) float Qs[64][65];
    __shared__ __align__(16) float Ds[64][64];

    const int bh = blockIdx.y;
    const int n0 = blockIdx.x * 64;
    const int tid = threadIdx.x;
    const int w = tid >> 5;
    const int lane = tid & 31;
    const int jf = lane & 15;
    const float sgn = (lane < 16) ? -1.0f : 1.0f;
    const unsigned FULL = 0xffffffffu;

    const int lt = tid >> 4;
    const int ld4 = (tid & 15) * 4;
    #pragma unroll
    for (int r = 0; r < 4; r++)
        *(float4*)&Ds[lt + 16 * r][ld4] =
            *(const float4*)&g_dots[(size_t)bh * (DD * DD) + (lt + 16 * r) * DD + ld4];

    #pragma unroll
    for (int r = 0; r < 8; r++) {
        const int trow = w * 8 + r;
        const int n = n0 + trow;
        const float* T = &g_trig[(size_t)n * 64];
        const float cx = T[jf], sx = T[16 + jf], cy = T[32 + jf], sy = T[48 + jf];
        const size_t base = ((size_t)bh * NN + n) * DD;
        float q0 = g_q[base + lane];
        float q1 = g_q[base + 32 + lane];
        float q0p = __shfl_xor_sync(FULL, q0, 16);
        float q1p = __shfl_xor_sync(FULL, q1, 16);
        Qs[trow][lane]      = q0 * cx + sgn * q0p * sx;
        Qs[trow][32 + lane] = q1 * cy + sgn * q1p * sy;
    }
    __syncthreads();

    const int tx = tid & 15;
    const int ty = tid >> 4;
    u64t acc[4][2];
    #pragma unroll
    for (int i = 0; i < 4; i++) { acc[i][0] = 0ull; acc[i][1] = 0ull; }

    #pragma unroll 4
    for (int k = 0; k < 64; k++) {
        float4 wv = *(const float4*)&Ds[k][tx * 4];
        u64t w2[2];
        w2[0] = ((const u64t*)&wv)[0];
        w2[1] = ((const u64t*)&wv)[1];
        #pragma unroll
        for (int i = 0; i < 4; i++) {
            u64t ap = pack2(Qs[ty * 4 + i][k]);
            acc[i][0] = ffma2(ap, w2[0], acc[i][0]);
            acc[i][1] = ffma2(ap, w2[1], acc[i][1]);
        }
    }

    #pragma unroll
    for (int i = 0; i < 4; i++) {
        float4 ov;
        unpack2(acc[i][0], ov.x, ov.y);
        unpack2(acc[i][1], ov.z, ov.w);
        *(float4*)&g_u[((size_t)bh * NN + n0 + ty * 4 + i) * DD + tx * 4] = ov;
    }
}

// ---------------------------------------------------------------------------
// Kernel D: out = gather(u) @ Wo^T + bo, f32x2 inner loop.
// ---------------------------------------------------------------------------
__global__ __launch_bounds__(256) void out_gemm(
    const float* __restrict__ Wo,
    const float* __restrict__ bo,
    float* __restrict__ out)
{
    __shared__ __align__(16) float Us[16][130];
    __shared__ __align__(16) float Ws[16][130];

    const int m0 = blockIdx.y * 128;
    const int j0 = blockIdx.x * 128;
    const int tid = threadIdx.x;
    const int tx = tid & 15;
    const int ty = tid >> 4;
    const int tk = tid & 3;
    const int tm = tid >> 2;

    u64t acc[4][8];
    #pragma unroll
    for (int ip = 0; ip < 4; ip++)
        #pragma unroll
        for (int j = 0; j < 8; j++) acc[ip][j] = 0ull;

    for (int kk = 0; kk < HD; kk += 16) {
        const int h = kk >> 6;
        const int d0 = kk & 63;
        #pragma unroll
        for (int half = 0; half < 2; half++) {
            int m = tm + 64 * half;
            int mg = m0 + m;
            int b = mg >> 13;
            int n = mg & (NN - 1);
            float4 uv = *(const float4*)&g_u[(((size_t)(b * HH + h)) * NN + n) * DD + d0 + 4 * tk];
            float4 wv = *(const float4*)&Wo[(size_t)(j0 + m) * HD + kk + 4 * tk];
            Us[4 * tk + 0][m] = uv.x; Us[4 * tk + 1][m] = uv.y;
            Us[4 * tk + 2][m] = uv.z; Us[4 * tk + 3][m] = uv.w;
            Ws[4 * tk + 0][m] = wv.x; Ws[4 * tk + 1][m] = wv.y;
            Ws[4 * tk + 2][m] = wv.z; Ws[4 * tk + 3][m] = wv.w;
        }
        __syncthreads();
        #pragma unroll
        for (int k = 0; k < 16; k++) {
            u64t a2[4], w2[8];
            #pragma unroll
            for (int ip = 0; ip < 4; ip++)
                a2[ip] = *(const u64t*)&Us[k][2 * ty + 32 * ip];
            #pragma unroll
            for (int j = 0; j < 8; j++)
                w2[j] = pack2(Ws[k][tx + 16 * j]);
            #pragma unroll
            for (int ip = 0; ip < 4; ip++)
                #pragma unroll
                for (int j = 0; j < 8; j++)
                    acc[ip][j] = ffma2(a2[ip], w2[j], acc[ip][j]);
        }
        __syncthreads();
    }

    #pragma unroll
    for (int ip = 0; ip < 4; ip++) {
        #pragma unroll
        for (int j = 0; j < 8; j++) {
            float lo, hi;
            unpack2(acc[ip][j], lo, hi);
            const int col = j0 + tx + 16 * j;
            const float bv = bo[col];
            #pragma unroll
            for (int hrow = 0; hrow < 2; hrow++) {
                int mg = m0 + 2 * ty + 32 * ip + hrow;
                out[(size_t)mg * CC + col] = (hrow ? hi : lo) + bv;
            }
        }
    }
}

// ---------------------------------------------------------------------------
extern "C" void kernel_launch(void* const* d_in, const int* in_sizes, int n_in,
                              void* d_out, int out_size)
{
    const float* ux  = (const float*)d_in[0];
    const float* pos = (const float*)d_in[1];
    const float* Wq  = (const float*)d_in[2];
    const float* Wk  = (const float*)d_in[3];
    const float* Wv  = (const float*)d_in[4];
    const float* Wo  = (const float*)d_in[5];
    const float* bo  = (const float*)d_in[6];
    float* out = (float*)d_out;

    trig_init<<<(NN * 16) / 256, 256>>>(pos);
    qkv_gemm<<<dim3(12, 256), 256>>>(ux, Wq, Wk, Wv);
    kv_dots<<<dim3(NCHUNK, BB * HH), 256>>>();
    reduce_dots<<<(BB * HH * DD * DD) / 256, 256>>>();
    q_dots<<<dim3(NN / 64, BB * HH), 256>>>();
    out_gemm<<<dim3(CC / 128, (BB * NN) / 128), 256>>>(Wo, bo, out);
}

// round 6
// speedup vs baseline: 1.5993x; 1.3651x over previous
#include <cuda_runtime.h>
#include <cuda_bf16.h>
#include <math.h>
#include <stdint.h>

#define BB 4
#define NN 8192
#define CC 256
#define HH 8
#define DD 64
#define HD 512
#define NCHUNK 16
#define CHK (NN / NCHUNK)   // 512

typedef unsigned long long u64t;

// ---------------------------------------------------------------------------
// Scratch (__device__ globals; allocation-free rule)
// ---------------------------------------------------------------------------
__device__ float g_q[BB * HH * NN * DD];            // [bh][n][d] fp32
__device__ float g_k[BB * HH * NN * DD];
__device__ float g_v[BB * HH * NN * DD];
__device__ float g_part[NCHUNK * BB * HH * DD * DD];
__device__ float g_dots[BB * HH * DD * DD];
__device__ float g_trig[NN * 64];                   // per n: cx[16] sx[16] cy[16] sy[16]

__device__ __nv_bfloat16 g_xh[32768 * 256];         // X split
__device__ __nv_bfloat16 g_xl[32768 * 256];
__device__ __nv_bfloat16 g_wh[1536 * 256];          // [Wq;Wk;Wv] split
__device__ __nv_bfloat16 g_wl[1536 * 256];
__device__ __nv_bfloat16 g_woh[256 * 512];          // Wo split
__device__ __nv_bfloat16 g_wol[256 * 512];
__device__ __nv_bfloat16 g_uh[32768 * 512];         // u split, [m][h*64+d]
__device__ __nv_bfloat16 g_ul[32768 * 512];

// ---------------------------------------------------------------------------
// helpers
// ---------------------------------------------------------------------------
__device__ __forceinline__ uint32_t smem_u32(const void* p) {
    uint32_t a;
    asm("{ .reg .u64 t; cvta.to.shared.u64 t, %1; cvt.u32.u64 %0, t; }" : "=r"(a) : "l"(p));
    return a;
}
__device__ __forceinline__ void ldm_x4(uint32_t& r0, uint32_t& r1, uint32_t& r2, uint32_t& r3,
                                       uint32_t addr) {
    asm volatile("ldmatrix.sync.aligned.m8n8.x4.shared.b16 {%0,%1,%2,%3}, [%4];"
                 : "=r"(r0), "=r"(r1), "=r"(r2), "=r"(r3) : "r"(addr));
}
__device__ __forceinline__ void mma_bf16(float* d, const uint32_t* a, const uint32_t* b) {
    asm volatile(
        "mma.sync.aligned.m16n8k16.row.col.f32.bf16.bf16.f32 "
        "{%0,%1,%2,%3}, {%4,%5,%6,%7}, {%8,%9}, {%0,%1,%2,%3};"
        : "+f"(d[0]), "+f"(d[1]), "+f"(d[2]), "+f"(d[3])
        : "r"(a[0]), "r"(a[1]), "r"(a[2]), "r"(a[3]), "r"(b[0]), "r"(b[1]));
}

// ---- packed f32x2 helpers (SIMT kernels) ----------------------------------
__device__ __forceinline__ u64t ffma2(u64t a, u64t b, u64t c) {
    u64t d;
    asm("fma.rn.f32x2 %0, %1, %2, %3;" : "=l"(d) : "l"(a), "l"(b), "l"(c));
    return d;
}
__device__ __forceinline__ u64t pack2(float x) {
    u64t d;
    asm("mov.b64 %0, {%1, %1};" : "=l"(d) : "r"(__float_as_uint(x)));
    return d;
}
__device__ __forceinline__ void unpack2(u64t v, float& lo, float& hi) {
    unsigned a, b;
    asm("mov.b64 {%0, %1}, %2;" : "=r"(a), "=r"(b) : "l"(v));
    lo = __uint_as_float(a);
    hi = __uint_as_float(b);
}
__device__ __forceinline__ void bf16split(float x, __nv_bfloat16& h, __nv_bfloat16& l) {
    h = __float2bfloat16_rn(x);
    l = __float2bfloat16_rn(x - __bfloat162float(h));
}

// ---------------------------------------------------------------------------
// trig table
// ---------------------------------------------------------------------------
__global__ __launch_bounds__(256) void trig_init(const float* __restrict__ pos)
{
    const int idx = blockIdx.x * 256 + threadIdx.x;
    const int n = idx >> 4;
    const int j = idx & 15;
    const float invf = exp2f(-(float)j * (13.2877123795494f / 16.0f));
    const float px = pos[n * 2 + 0];
    const float py = pos[n * 2 + 1];
    float cx, sx, cy, sy;
    sincosf(px * 64.0f * invf, &sx, &cx);
    sincosf(py * 64.0f * invf, &sy, &cy);
    float* T = &g_trig[(size_t)n * 64];
    T[j] = cx; T[16 + j] = sx; T[32 + j] = cy; T[48 + j] = sy;
}

// ---------------------------------------------------------------------------
// prep: split X and weights into bf16 hi/lo
// ---------------------------------------------------------------------------
__global__ __launch_bounds__(256) void prep_x(const float* __restrict__ X)
{
    const size_t i4 = ((size_t)blockIdx.x * 256 + threadIdx.x) * 4;
    float4 v = *(const float4*)&X[i4];
    __nv_bfloat16 h0, l0, h1, l1, h2, l2, h3, l3;
    bf16split(v.x, h0, l0); bf16split(v.y, h1, l1);
    bf16split(v.z, h2, l2); bf16split(v.w, h3, l3);
    uint2 ph, pl;
    ph.x = (uint32_t)__bfloat16_as_ushort(h0) | ((uint32_t)__bfloat16_as_ushort(h1) << 16);
    ph.y = (uint32_t)__bfloat16_as_ushort(h2) | ((uint32_t)__bfloat16_as_ushort(h3) << 16);
    pl.x = (uint32_t)__bfloat16_as_ushort(l0) | ((uint32_t)__bfloat16_as_ushort(l1) << 16);
    pl.y = (uint32_t)__bfloat16_as_ushort(l2) | ((uint32_t)__bfloat16_as_ushort(l3) << 16);
    *(uint2*)&g_xh[i4] = ph;
    *(uint2*)&g_xl[i4] = pl;
}

__global__ __launch_bounds__(256) void prep_w(
    const float* __restrict__ Wq, const float* __restrict__ Wk,
    const float* __restrict__ Wv, const float* __restrict__ Wo)
{
    const size_t i4 = ((size_t)blockIdx.x * 256 + threadIdx.x) * 4;   // < 524288
    const float* src;
    __nv_bfloat16 *dh, *dl;
    size_t off;
    if (i4 < 393216) {
        int seg = (int)(i4 / 131072);
        off = i4 % 131072;
        src = (seg == 0) ? Wq : (seg == 1) ? Wk : Wv;
        dh = g_wh + (size_t)seg * 131072;
        dl = g_wl + (size_t)seg * 131072;
    } else {
        off = i4 - 393216;
        src = Wo;
        dh = g_woh;
        dl = g_wol;
    }
    float4 v = *(const float4*)&src[off];
    __nv_bfloat16 h0, l0, h1, l1, h2, l2, h3, l3;
    bf16split(v.x, h0, l0); bf16split(v.y, h1, l1);
    bf16split(v.z, h2, l2); bf16split(v.w, h3, l3);
    uint2 ph, pl;
    ph.x = (uint32_t)__bfloat16_as_ushort(h0) | ((uint32_t)__bfloat16_as_ushort(h1) << 16);
    ph.y = (uint32_t)__bfloat16_as_ushort(h2) | ((uint32_t)__bfloat16_as_ushort(h3) << 16);
    pl.x = (uint32_t)__bfloat16_as_ushort(l0) | ((uint32_t)__bfloat16_as_ushort(l1) << 16);
    pl.y = (uint32_t)__bfloat16_as_ushort(l2) | ((uint32_t)__bfloat16_as_ushort(l3) << 16);
    *(uint2*)&dh[off] = ph;
    *(uint2*)&dl[off] = pl;
}

// ---------------------------------------------------------------------------
// HMMA GEMM: D[J, tok] = sum_k A[J,k] * B[tok,k], bf16 2-term split (3 passes).
// Block tile 128(J) x 128(tok), K slab 64. 8 warps = 4(m) x 2(n), warp 32x64.
// All smem STATIC (<= 48KB): load tiles 36864B; epilogue reuses it as a
// 64x132 fp32 stage, two token-half passes.
// MODE 0: A = W_cat [1536 x 256], B = X [32768 x 256] -> scatter to g_q/g_k/g_v
// MODE 1: A = Wo    [ 256 x 512], B = u [32768 x 512] -> out + bias
// ---------------------------------------------------------------------------
template <int MODE>
__global__ __launch_bounds__(256) void gemm_mma(const float* __restrict__ bias,
                                                float* __restrict__ outp)
{
    constexpr int KTOT = (MODE == 0) ? 256 : 512;
    constexpr int SASTRIDE = 72;   // bf16/row (64+8 pad); 144B stride: ldmatrix conflict-free

    __shared__ __align__(16) char sm[128 * SASTRIDE * 2 * 2];   // 36864 B
    __nv_bfloat16 (*sA)[SASTRIDE] = (__nv_bfloat16(*)[SASTRIDE])sm;
    __nv_bfloat16 (*sB)[SASTRIDE] = (__nv_bfloat16(*)[SASTRIDE])(sm + 128 * SASTRIDE * 2);

    const int tid = threadIdx.x;
    const int wid = tid >> 5;
    const int lane = tid & 31;
    const int wm = wid & 3;        // warp m (J) index: 4
    const int wn = wid >> 2;       // warp n (tok) index: 2
    const int J0 = blockIdx.x * 128;
    const int T0 = blockIdx.y * 128;

    float acc[2][8][4];
    #pragma unroll
    for (int am = 0; am < 2; am++)
        #pragma unroll
        for (int bn = 0; bn < 8; bn++)
            #pragma unroll
            for (int c = 0; c < 4; c++) acc[am][bn][c] = 0.0f;

    const int lrow = tid >> 1;       // 0..127
    const int lhalf = tid & 1;       // 64B half of the 128B row

    for (int pass = 0; pass < 3; pass++) {
        const __nv_bfloat16* Asrc;
        const __nv_bfloat16* Bsrc;
        if (MODE == 0) {
            Asrc = (pass == 1) ? g_wl : g_wh;
            Bsrc = (pass == 2) ? g_xl : g_xh;
        } else {
            Asrc = (pass == 1) ? g_wol : g_woh;
            Bsrc = (pass == 2) ? g_ul : g_uh;
        }
        for (int kk = 0; kk < KTOT; kk += 64) {
            {
                const int4* src = (const int4*)(Asrc + (size_t)(J0 + lrow) * KTOT + kk) + lhalf * 4;
                int4* dst = (int4*)&sA[lrow][lhalf * 32];
                #pragma unroll
                for (int q = 0; q < 4; q++) dst[q] = src[q];
            }
            {
                const int4* src = (const int4*)(Bsrc + (size_t)(T0 + lrow) * KTOT + kk) + lhalf * 4;
                int4* dst = (int4*)&sB[lrow][lhalf * 32];
                #pragma unroll
                for (int q = 0; q < 4; q++) dst[q] = src[q];
            }
            __syncthreads();
            #pragma unroll
            for (int ks = 0; ks < 4; ks++) {
                uint32_t af[2][4], bf[8][2];
                #pragma unroll
                for (int am = 0; am < 2; am++) {
                    const int r = wm * 32 + am * 16 + (lane & 15);
                    const int c = ks * 16 + ((lane >> 4) << 3);
                    ldm_x4(af[am][0], af[am][1], af[am][2], af[am][3], smem_u32(&sA[r][c]));
                }
                #pragma unroll
                for (int bn = 0; bn < 4; bn++) {
                    const int r = wn * 64 + bn * 16 + ((lane >> 4) << 3) + (lane & 7);
                    const int c = ks * 16 + (((lane >> 3) & 1) << 3);
                    ldm_x4(bf[2 * bn][0], bf[2 * bn][1], bf[2 * bn + 1][0], bf[2 * bn + 1][1],
                           smem_u32(&sB[r][c]));
                }
                #pragma unroll
                for (int am = 0; am < 2; am++)
                    #pragma unroll
                    for (int bn = 0; bn < 8; bn++)
                        mma_bf16(acc[am][bn], af[am], bf[bn]);
            }
            __syncthreads();
        }
    }

    // Epilogue: two half-passes over tokens, staging transposed in smem.
    float* stage = (float*)sm;   // 64 x 132 fp32 = 33792 B (fits static region)
    #pragma unroll 1
    for (int half = 0; half < 2; half++) {
        __syncthreads();
        if (wn == half) {
            #pragma unroll
            for (int am = 0; am < 2; am++)
                #pragma unroll
                for (int bn = 0; bn < 8; bn++)
                    #pragma unroll
                    for (int c = 0; c < 4; c++) {
                        const int ml = wm * 32 + am * 16 + (lane >> 2) + ((c >> 1) << 3);
                        const int nl = bn * 8 + (lane & 3) * 2 + (c & 1);
                        stage[nl * 132 + ml] = acc[am][bn][c];
                    }
        }
        __syncthreads();
        const int tok_l = tid >> 2;          // 0..63
        const int qg = tid & 3;              // 32-J group
        const float* srow = &stage[tok_l * 132 + qg * 32];
        const int m = T0 + half * 64 + tok_l;
        const int J = J0 + qg * 32;
        if (MODE == 0) {
            const int which = J >> 9;
            const int h = (J >> 6) & 7;
            const int d = J & 63;
            const int b = m >> 13;
            const int n = m & (NN - 1);
            float* dst = ((which == 0) ? g_q : (which == 1) ? g_k : g_v)
                         + (((size_t)(b * HH + h)) * NN + n) * DD + d;
            #pragma unroll
            for (int dd = 0; dd < 32; dd += 4)
                *(float4*)&dst[dd] = *(const float4*)&srow[dd];
        } else {
            float* dst = outp + (size_t)m * CC + J;
            #pragma unroll
            for (int dd = 0; dd < 32; dd += 4) {
                float4 v = *(const float4*)&srow[dd];
                float4 bv = *(const float4*)&bias[J + dd];
                v.x += bv.x; v.y += bv.y; v.z += bv.z; v.w += bv.w;
                *(float4*)&dst[dd] = v;
            }
        }
    }
}

// ---------------------------------------------------------------------------
// kv_dots: fused instance-norm(K,V) + RoPE(K), partial K^T V per chunk
// ---------------------------------------------------------------------------
__global__ __launch_bounds__(256) void kv_dots()
{
    __shared__ __align__(16) float Ks[16][64];
    __shared__ __align__(16) float Vs[16][64];

    const int chunk = blockIdx.x;
    const int bh = blockIdx.y;
    const int tid = threadIdx.x;
    const int w = tid >> 5;
    const int lane = tid & 31;
    const int jf = lane & 15;
    const float sgn = (lane < 16) ? -1.0f : 1.0f;
    const unsigned FULL = 0xffffffffu;

    const int tx = tid & 15;
    const int ty = tid >> 4;
    const int lt = tid >> 4;
    const int ld4 = (tid & 15) * 4;

    const size_t nbase = (size_t)bh * NN + (size_t)chunk * CHK;

    u64t acc[4][2];
    #pragma unroll
    for (int i = 0; i < 4; i++) { acc[i][0] = 0ull; acc[i][1] = 0ull; }

    for (int s = 0; s < CHK; s += 16) {
        *(float4*)&Ks[lt][ld4] = *(const float4*)&g_k[(nbase + s + lt) * DD + ld4];
        *(float4*)&Vs[lt][ld4] = *(const float4*)&g_v[(nbase + s + lt) * DD + ld4];
        __syncthreads();

        #pragma unroll
        for (int r = 0; r < 2; r++) {
            const int row = w * 2 + r;
            const int n = chunk * CHK + s + row;
            const float* T = &g_trig[(size_t)n * 64];
            const float cx = T[jf], sx = T[16 + jf], cy = T[32 + jf], sy = T[48 + jf];
            {
                float k0 = Ks[row][lane], k1 = Ks[row][32 + lane];
                float su = k0 + k1, ss = k0 * k0 + k1 * k1;
                #pragma unroll
                for (int o = 16; o > 0; o >>= 1) {
                    su += __shfl_xor_sync(FULL, su, o);
                    ss += __shfl_xor_sync(FULL, ss, o);
                }
                float mean = su * (1.0f / 64.0f);
                float var = ss * (1.0f / 64.0f) - mean * mean;
                float inv = rsqrtf(var + 1e-5f);
                k0 = (k0 - mean) * inv;
                k1 = (k1 - mean) * inv;
                float k0p = __shfl_xor_sync(FULL, k0, 16);
                float k1p = __shfl_xor_sync(FULL, k1, 16);
                Ks[row][lane]      = k0 * cx + sgn * k0p * sx;
                Ks[row][32 + lane] = k1 * cy + sgn * k1p * sy;
            }
            {
                float v0 = Vs[row][lane], v1 = Vs[row][32 + lane];
                float su = v0 + v1, ss = v0 * v0 + v1 * v1;
                #pragma unroll
                for (int o = 16; o > 0; o >>= 1) {
                    su += __shfl_xor_sync(FULL, su, o);
                    ss += __shfl_xor_sync(FULL, ss, o);
                }
                float mean = su * (1.0f / 64.0f);
                float var = ss * (1.0f / 64.0f) - mean * mean;
                float inv = rsqrtf(var + 1e-5f);
                Vs[row][lane]      = (v0 - mean) * inv;
                Vs[row][32 + lane] = (v1 - mean) * inv;
            }
        }
        __syncthreads();

        #pragma unroll
        for (int t = 0; t < 16; t++) {
            float4 av = *(const float4*)&Ks[t][ty * 4];
            float4 wv = *(const float4*)&Vs[t][tx * 4];
            u64t w2[2];
            w2[0] = ((const u64t*)&wv)[0];
            w2[1] = ((const u64t*)&wv)[1];
            float a[4] = {av.x, av.y, av.z, av.w};
            #pragma unroll
            for (int i = 0; i < 4; i++) {
                u64t ap = pack2(a[i]);
                acc[i][0] = ffma2(ap, w2[0], acc[i][0]);
                acc[i][1] = ffma2(ap, w2[1], acc[i][1]);
            }
        }
        __syncthreads();
    }

    float* P = &g_part[((size_t)chunk * (BB * HH) + bh) * (DD * DD)];
    #pragma unroll
    for (int i = 0; i < 4; i++) {
        float4 ov;
        unpack2(acc[i][0], ov.x, ov.y);
        unpack2(acc[i][1], ov.z, ov.w);
        *(float4*)&P[(ty * 4 + i) * DD + tx * 4] = ov;
    }
}

__global__ __launch_bounds__(256) void reduce_dots()
{
    const int i = blockIdx.x * 256 + threadIdx.x;
    float s = 0.0f;
    #pragma unroll
    for (int c = 0; c < NCHUNK; c++)
        s += g_part[(size_t)c * (BB * HH * DD * DD) + i];
    g_dots[i] = s * (1.0f / (float)NN);
}

// ---------------------------------------------------------------------------
// q_dots: u = rope(q) @ dots; outputs u as bf16 hi/lo at [m][h*64+d]
// ---------------------------------------------------------------------------
__global__ __launch_bounds__(256) void q_dots()
{
    __shared__ __align__(16) float Qs[64][65];
    __shared__ __align__(16) float Ds[64][64];

    const int bh = blockIdx.y;
    const int n0 = blockIdx.x * 64;
    const int tid = threadIdx.x;
    const int w = tid >> 5;
    const int lane = tid & 31;
    const int jf = lane & 15;
    const float sgn = (lane < 16) ? -1.0f : 1.0f;
    const unsigned FULL = 0xffffffffu;

    const int lt = tid >> 4;
    const int ld4 = (tid & 15) * 4;
    #pragma unroll
    for (int r = 0; r < 4; r++)
        *(float4*)&Ds[lt + 16 * r][ld4] =
            *(const float4*)&g_dots[(size_t)bh * (DD * DD) + (lt + 16 * r) * DD + ld4];

    #pragma unroll
    for (int r = 0; r < 8; r++) {
        const int trow = w * 8 + r;
        const int n = n0 + trow;
        const float* T = &g_trig[(size_t)n * 64];
        const float cx = T[jf], sx = T[16 + jf], cy = T[32 + jf], sy = T[48 + jf];
        const size_t base = ((size_t)bh * NN + n) * DD;
        float q0 = g_q[base + lane];
        float q1 = g_q[base + 32 + lane];
        float q0p = __shfl_xor_sync(FULL, q0, 16);
        float q1p = __shfl_xor_sync(FULL, q1, 16);
        Qs[trow][lane]      = q0 * cx + sgn * q0p * sx;
        Qs[trow][32 + lane] = q1 * cy + sgn * q1p * sy;
    }
    __syncthreads();

    const int tx = tid & 15;
    const int ty = tid >> 4;
    u64t acc[4][2];
    #pragma unroll
    for (int i = 0; i < 4; i++) { acc[i][0] = 0ull; acc[i][1] = 0ull; }

    #pragma unroll 4
    for (int k = 0; k < 64; k++) {
        float4 wv = *(const float4*)&Ds[k][tx * 4];
        u64t w2[2];
        w2[0] = ((const u64t*)&wv)[0];
        w2[1] = ((const u64t*)&wv)[1];
        #pragma unroll
        for (int i = 0; i < 4; i++) {
            u64t ap = pack2(Qs[ty * 4 + i][k]);
            acc[i][0] = ffma2(ap, w2[0], acc[i][0]);
            acc[i][1] = ffma2(ap, w2[1], acc[i][1]);
        }
    }

    const int b = bh >> 3;
    const int h = bh & 7;
    #pragma unroll
    for (int i = 0; i < 4; i++) {
        float4 ov;
        unpack2(acc[i][0], ov.x, ov.y);
        unpack2(acc[i][1], ov.z, ov.w);
        const size_t m = (size_t)b * NN + (n0 + ty * 4 + i);
        const size_t off = m * HD + h * DD + tx * 4;
        __nv_bfloat16 h0, l0, h1, l1, h2, l2, h3, l3;
        bf16split(ov.x, h0, l0); bf16split(ov.y, h1, l1);
        bf16split(ov.z, h2, l2); bf16split(ov.w, h3, l3);
        uint2 ph, pl;
        ph.x = (uint32_t)__bfloat16_as_ushort(h0) | ((uint32_t)__bfloat16_as_ushort(h1) << 16);
        ph.y = (uint32_t)__bfloat16_as_ushort(h2) | ((uint32_t)__bfloat16_as_ushort(h3) << 16);
        pl.x = (uint32_t)__bfloat16_as_ushort(l0) | ((uint32_t)__bfloat16_as_ushort(l1) << 16);
        pl.y = (uint32_t)__bfloat16_as_ushort(l2) | ((uint32_t)__bfloat16_as_ushort(l3) << 16);
        *(uint2*)&g_uh[off] = ph;
        *(uint2*)&g_ul[off] = pl;
    }
}

// ---------------------------------------------------------------------------
extern "C" void kernel_launch(void* const* d_in, const int* in_sizes, int n_in,
                              void* d_out, int out_size)
{
    const float* ux  = (const float*)d_in[0];
    const float* pos = (const float*)d_in[1];
    const float* Wq  = (const float*)d_in[2];
    const float* Wk  = (const float*)d_in[3];
    const float* Wv  = (const float*)d_in[4];
    const float* Wo  = (const float*)d_in[5];
    const float* bo  = (const float*)d_in[6];
    float* out = (float*)d_out;

    trig_init<<<(NN * 16) / 256, 256>>>(pos);
    prep_x<<<(32768 * 256) / (256 * 4), 256>>>(ux);
    prep_w<<<524288 / (256 * 4), 256>>>(Wq, Wk, Wv, Wo);
    gemm_mma<0><<<dim3(12, 256), 256>>>(nullptr, nullptr);
    kv_dots<<<dim3(NCHUNK, BB * HH), 256>>>();
    reduce_dots<<<(BB * HH * DD * DD) / 256, 256>>>();
    q_dots<<<dim3(NN / 64, BB * HH), 256>>>();
    gemm_mma<1><<<dim3(2, 256), 256>>>(bo, out);
}